// round 14
// baseline (speedup 1.0000x reference)
#include <cuda_runtime.h>
#include <cuda_bf16.h>
#include <math.h>
#include <stdint.h>

#define NN 1000
#define FF 64
#define SS 192          // B*T snapshots
#define EE 16000
#define CC 10
#define BBATCH 16
#define JTOT 768000     // T*N*F
#define LN_EPS 1e-5f
#define FCHUNKS 384
#define CHUNK_J 2000

// ---------------- scratch (static device globals; no allocation) -------------
__device__ float g_basis[8][SS * NN * FF];
__device__ float g_h[SS * NN * FF];
__device__ __nv_bfloat16 g_Bpack[2][9][8192];   // [hi/lo][slot][swizzled 128n x 64k]
__device__ float g_bcat[128];
__device__ int   g_offA[NN + 8], g_offB[NN + 8];   // padded for 16B cp.async reads
__device__ uint16_t g_adjA16[EE + 8];            // prop_out srcs (grouped by dst)
__device__ uint16_t g_adjB16[EE + 8];            // prop_in  srcs (grouped by row)
__device__ float g_invdeg_out[NN];
__device__ float g_inv_deg_in[NN];
__device__ float g_partial[FCHUNKS * BBATCH * CC];

// ---------------- helpers -----------------------------------------------------
__device__ __forceinline__ uint32_t smem_u32(const void* p) {
    uint32_t a;
    asm("{ .reg .u64 t; cvta.to.shared.u64 t, %1; cvt.u32.u64 %0, t; }" : "=r"(a) : "l"(p));
    return a;
}
#define SWZ128(o) ((o) ^ (((o) >> 3) & 0x70))

__device__ __forceinline__ void cpa16(uint32_t dst, const void* src) {
    asm volatile("cp.async.cg.shared.global [%0], [%1], 16;" :: "r"(dst), "l"(src));
}
__device__ __forceinline__ void cpa_commit_wait() {
    asm volatile("cp.async.commit_group;" ::: "memory");
    asm volatile("cp.async.wait_group 0;" ::: "memory");
}

__device__ __forceinline__ void ldsm4(uint32_t* r, uint32_t addr) {
    asm volatile("ldmatrix.sync.aligned.m8n8.x4.shared.b16 {%0,%1,%2,%3}, [%4];"
        : "=r"(r[0]), "=r"(r[1]), "=r"(r[2]), "=r"(r[3]) : "r"(addr));
}

__device__ __forceinline__ void mma_bf16(float* d, const uint32_t* a, const uint32_t* b) {
    asm volatile(
        "mma.sync.aligned.m16n8k16.row.col.f32.bf16.bf16.f32 "
        "{%0,%1,%2,%3}, {%4,%5,%6,%7}, {%8,%9}, {%0,%1,%2,%3};"
        : "+f"(d[0]), "+f"(d[1]), "+f"(d[2]), "+f"(d[3])
        : "r"(a[0]), "r"(a[1]), "r"(a[2]), "r"(a[3]), "r"(b[0]), "r"(b[1]));
}

// ---------------- fused graph preprocessing (zero+count+scan, 1 block) --------
__global__ void k_pre(const int* __restrict__ ei) {
    __shared__ int sdo[NN], sdi[NN];
    __shared__ int sA[1024], sB[1024];
    int i = threadIdx.x;
    if (i < NN) { sdo[i] = 0; sdi[i] = 0; }
    __syncthreads();
    for (int e = i; e < EE; e += 1024) {
        atomicAdd(&sdo[ei[e]], 1);
        atomicAdd(&sdi[ei[EE + e]], 1);
    }
    __syncthreads();
    int da = (i < NN) ? sdi[i] : 0;
    int db = (i < NN) ? sdo[i] : 0;
    sA[i] = da; sB[i] = db;
    __syncthreads();
    for (int off = 1; off < 1024; off <<= 1) {
        int va = (i >= off) ? sA[i - off] : 0;
        int vb = (i >= off) ? sB[i - off] : 0;
        __syncthreads();
        sA[i] += va; sB[i] += vb;
        __syncthreads();
    }
    if (i < NN) {
        g_offA[i] = sA[i] - da;
        g_offB[i] = sB[i] - db;
        g_inv_deg_in[i] = 1.0f / (float)da;
        g_invdeg_out[i] = 1.0f / (float)sdo[i];
    }
    if (i == 0) { g_offA[NN] = sA[1023]; g_offB[NN] = sB[1023]; }
}

// deterministic CSR build: stage all edges in smem, one warp per node, ballot compaction
__global__ void k_build(const int* __restrict__ ei) {
    extern __shared__ int2 se[];                   // 16000 x 8B = 128KB
    int tid = threadIdx.x;
    for (int i = tid; i < EE; i += blockDim.x)
        se[i] = make_int2(ei[i], ei[EE + i]);
    __syncthreads();
    int warp = blockIdx.x * (blockDim.x >> 5) + (tid >> 5);
    int lane = tid & 31;
    if (warp >= NN) return;
    int n = warp;
    int pa = g_offA[n], pb = g_offB[n];
    for (int e0 = 0; e0 < EE; e0 += 32) {
        int2 rc = se[e0 + lane];
        unsigned mA = __ballot_sync(0xffffffffu, rc.y == n);
        unsigned mB = __ballot_sync(0xffffffffu, rc.x == n);
        if (rc.y == n) {
            int pos = pa + __popc(mA & ((1u << lane) - 1));
            g_adjA16[pos] = (uint16_t)rc.x;
        }
        if (rc.x == n) {
            int pos = pb + __popc(mB & ((1u << lane) - 1));
            g_adjB16[pos] = (uint16_t)rc.y;
        }
        pa += __popc(mA); pb += __popc(mB);
    }
}

// pack weights into bf16 hi/lo images (SW128-swizzled, [n][k] rows of 128B)
__global__ void k_packW(const float* __restrict__ Wz, const float* __restrict__ bz,
                        const float* __restrict__ Wh, const float* __restrict__ bh) {
    int i = blockIdx.x * blockDim.x + threadIdx.x;
    if (i < 128) g_bcat[i] = (i < 64) ? bz[i] : bh[i - 64];
    if (i >= 9 * 8192) return;
    int slot = i >> 13;
    int r = i & 8191;
    int n = r >> 6, k = r & 63;
    const float* W = (n < 64) ? Wz : Wh;
    int f = n & 63;
    float v;
    if (slot == 0) {
        v = W[(0 * 5 + 0) * 128 * 64 + k * 64 + f]
          + W[(1 * 5 + 0) * 128 * 64 + k * 64 + f];
    } else {
        int kc = (slot + 1) >> 1;
        int dir = (slot - 1) & 1;
        v = W[(dir * 5 + kc) * 128 * 64 + k * 64 + f];
    }
    __nv_bfloat16 hi = __float2bfloat16(v);
    __nv_bfloat16 lo = __float2bfloat16(v - __bfloat162float(hi));
    uint32_t off = SWZ128((uint32_t)(n * 128 + k * 2));
    g_Bpack[0][slot][off >> 1] = hi;
    g_Bpack[1][slot][off >> 1] = lo;
}

// ---------------- Chebyshev propagation (16-feat blocks, 2 CTAs/SM) -----------
// blockIdx = (s, dir, quarter). Values = 1000 x 16 feats (64KB) + adj (32KB) +
// offsets + inv-deg = 104KB -> 2 CTAs/SM. Warp: 4 edge-slots (el = lane>>3),
// 8 float2 feature-pairs per lane; 2 shfl_xor rounds merge the edge-slots.
// dir0 plane pre-scaled by 1/deg_out[node].
#define ADJ_OFF  64000      // 16000 uint16
#define OFF_OFF  96032      // 1008 ints  (16B aligned)
#define INV_OFF  100064     // 1000 floats
#define PROP_SMEM 104064

__global__ void __launch_bounds__(1024, 2) a_prop(const float* __restrict__ x, int level) {
    extern __shared__ float sv[];
    float2* sv2 = (float2*)sv;                      // [1000][8]
    uint16_t* sadj = (uint16_t*)((char*)sv + ADJ_OFF);
    int* soff = (int*)((char*)sv + OFF_OFF);
    float* sinv = (float*)((char*)sv + INV_OFF);
    int s = blockIdx.x, dir = blockIdx.y, quarter = blockIdx.z;
    int dst_slot = 2 * level - 1 + dir;
    const float* src;
    const float* prev = nullptr;
    if (level == 1) {
        src = x + (size_t)s * NN * FF;
    } else {
        int ssrc = 2 * (level - 1) - 1 + dir;
        src = g_basis[ssrc - 1] + (size_t)s * NN * FF;
        if (level == 2) prev = x + (size_t)s * NN * FF;
        else prev = g_basis[(2 * (level - 2) - 1) - 1] + (size_t)s * NN * FF;
    }
    uint32_t sb = smem_u32(sv);
    int tid = threadIdx.x;
    // values: 4000 x 16B chunks (16 feats per node)
    #pragma unroll
    for (int it = 0; it < 4; it++) {
        int i = tid + it * 1024;
        if (i < 4000) {
            int n = i >> 2, q = i & 3;
            cpa16(sb + (uint32_t)(n * 64 + q * 16),
                  src + (size_t)n * FF + quarter * 16 + q * 4);
        }
    }
    // adjacency: 2000 x 16B chunks
    {
        const uint16_t* adj = dir ? g_adjB16 : g_adjA16;
        #pragma unroll
        for (int it = 0; it < 2; it++) {
            int i = tid + it * 1024;
            if (i < 2000)
                cpa16(sb + ADJ_OFF + i * 16, adj + i * 8);
        }
    }
    if (tid < 251) {
        const int* offsrc = dir ? g_offB : g_offA;
        cpa16(sb + OFF_OFF + tid * 16, offsrc + tid * 4);
    }
    if (tid >= 512 && tid < 762) {
        const float* invsrc = dir ? g_inv_deg_in : g_invdeg_out;
        int i = tid - 512;
        cpa16(sb + INV_OFF + i * 16, invsrc + i * 4);
    }
    cpa_commit_wait();
    __syncthreads();

    if (dir == 0) {     // pre-scale values by 1/deg_out[node]
        #pragma unroll
        for (int it = 0; it < 16; it++) {
            int i = tid + it * 1024;
            if (i < 16000) sv[i] *= sinv[i >> 4];
        }
        __syncthreads();
    }

    int lane = tid & 31;
    int w = tid >> 5;                     // 32 warps
    int el = lane >> 3, fp = lane & 7;    // edge-slot 0..3, feature-pair 0..7
    float* out = g_basis[dst_slot - 1] + (size_t)s * NN * FF;

    for (int n = w; n < NN; n += 32) {
        int b = soff[n], e = soff[n + 1];
        float ax = 0.f, ay = 0.f;
        for (int j = b + el; j < e; j += 4) {
            int s0 = sadj[j];
            float2 v = sv2[s0 * 8 + fp];
            ax += v.x; ay += v.y;
        }
        ax += __shfl_xor_sync(0xffffffffu, ax, 8);
        ay += __shfl_xor_sync(0xffffffffu, ay, 8);
        ax += __shfl_xor_sync(0xffffffffu, ax, 16);
        ay += __shfl_xor_sync(0xffffffffu, ay, 16);
        if (dir == 1) { float iv = sinv[n]; ax *= iv; ay *= iv; }
        if (el == 0) {
            int f = quarter * 16 + fp * 2;
            float2 r;
            if (level == 1) { r.x = ax; r.y = ay; }
            else {
                float2 pv = *(const float2*)(prev + n * FF + f);
                r.x = 2.0f * ax - pv.x;
                r.y = 2.0f * ay - pv.y;
            }
            *(float2*)(out + n * FF + f) = r;
        }
    }
}

// ---------------- mma.sync bf16 GEMM: 128-thr blocks, 2 CTAs/SM ---------------
// A prefetched into registers (LDG, hidden behind mma), converted reg->smem.
// B double-buffered via cp.async. 3-pass bf16 split, fp32 accum, fused epilogue.
#define SM_AHI 0            // 8192
#define SM_ALO 8192         // 8192
#define SM_B   16384        // 2 x 32768 (hi at +0, lo at +16384)
#define SM_TOTAL_GEMM 81920

__global__ void __launch_bounds__(128, 2) k_gemm_mma(const float* __restrict__ x,
                                                     const float* __restrict__ ln_g,
                                                     const float* __restrict__ ln_b) {
    extern __shared__ char smem[];
    uint32_t sb = smem_u32(smem);
    const int tid = threadIdx.x;
    const int wid = tid >> 5, lane = tid & 31;
    const int s = blockIdx.x >> 4;
    const int row0 = (blockIdx.x & 15) << 6;    // 64-row tile
    const int m0 = wid << 4;                    // warp rows within tile

    float acc[16][4];
    #pragma unroll
    for (int t = 0; t < 16; t++)
        #pragma unroll
        for (int c = 0; c < 4; c++) acc[t][c] = 0.0f;

    const uint32_t a_rowoff = (uint32_t)((m0 + (lane & 15)) * 128 + ((lane >> 4) * 16));
    const uint32_t b_rowoff = (uint32_t)((((lane >> 4) * 8 + (lane & 7)) * 128) + (((lane >> 3) & 1) * 16));

    float4 pf[8];
    auto ldA = [&](int slot) {
        const float* plane = (slot == 0) ? (x + (size_t)s * NN * FF)
                                         : (g_basis[slot - 1] + (size_t)s * NN * FF);
        #pragma unroll
        for (int i = 0; i < 8; i++) {
            int j = tid + i * 128;               // 1024 chunks: 64 rows x 16 quads
            int node = row0 + (j >> 4);
            pf[i] = (node < NN) ? *(const float4*)(plane + (size_t)node * FF + (j & 15) * 4)
                                : make_float4(0.f, 0.f, 0.f, 0.f);
        }
    };
    auto issueB = [&](int slot, int buf) {
        const char* bh = (const char*)&g_Bpack[0][slot][0];
        const char* bl = (const char*)&g_Bpack[1][slot][0];
        #pragma unroll
        for (int i = 0; i < 8; i++) {
            int j = tid + i * 128;               // 1024 chunks each image
            cpa16(sb + SM_B + buf * 32768 + j * 16, bh + j * 16);
            cpa16(sb + SM_B + buf * 32768 + 16384 + j * 16, bl + j * 16);
        }
        asm volatile("cp.async.commit_group;" ::: "memory");
    };

    ldA(0);
    issueB(0, 0);
    for (int slot = 0; slot < 9; slot++) {
        int buf = slot & 1;
        __syncthreads();                         // AHI/ALO free of prev-slot readers
        #pragma unroll
        for (int i = 0; i < 8; i++) {
            int j = tid + i * 128;
            int m = j >> 4, kq = j & 15;
            float4 v = pf[i];
            __nv_bfloat16 h0 = __float2bfloat16(v.x);
            __nv_bfloat16 h1 = __float2bfloat16(v.y);
            __nv_bfloat16 h2 = __float2bfloat16(v.z);
            __nv_bfloat16 h3 = __float2bfloat16(v.w);
            __nv_bfloat16 l0 = __float2bfloat16(v.x - __bfloat162float(h0));
            __nv_bfloat16 l1 = __float2bfloat16(v.y - __bfloat162float(h1));
            __nv_bfloat16 l2 = __float2bfloat16(v.z - __bfloat162float(h2));
            __nv_bfloat16 l3 = __float2bfloat16(v.w - __bfloat162float(h3));
            uint32_t off = SWZ128((uint32_t)(m * 128 + kq * 8));
            *(__nv_bfloat162*)(smem + SM_AHI + off)     = __halves2bfloat162(h0, h1);
            *(__nv_bfloat162*)(smem + SM_AHI + off + 4) = __halves2bfloat162(h2, h3);
            *(__nv_bfloat162*)(smem + SM_ALO + off)     = __halves2bfloat162(l0, l1);
            *(__nv_bfloat162*)(smem + SM_ALO + off + 4) = __halves2bfloat162(l2, l3);
        }
        if (slot < 8) {
            ldA(slot + 1);                       // LDG prefetch; consumed next iter
            issueB(slot + 1, buf ^ 1);
            asm volatile("cp.async.wait_group 1;" ::: "memory");
        } else {
            asm volatile("cp.async.wait_group 0;" ::: "memory");
        }
        __syncthreads();

        uint32_t bBH = sb + SM_B + buf * 32768;
        uint32_t bBL = bBH + 16384;
        #pragma unroll
        for (int kk = 0; kk < 4; kk++) {
            const uint32_t kbase = kk * 32;
            uint32_t aAh[4], aAl[4];
            ldsm4(aAh, sb + SM_AHI + SWZ128(a_rowoff + kbase));
            ldsm4(aAl, sb + SM_ALO + SWZ128(a_rowoff + kbase));
            uint32_t bF[8][4];
            #pragma unroll
            for (int p = 0; p < 8; p++)
                ldsm4(bF[p], bBH + SWZ128(b_rowoff + p * 2048 + kbase));
            #pragma unroll
            for (int t = 0; t < 16; t++) {
                const uint32_t* bf = &bF[t >> 1][(t & 1) * 2];
                mma_bf16(acc[t], aAh, bf);     // Ahi * Bhi
                mma_bf16(acc[t], aAl, bf);     // Alo * Bhi
            }
            #pragma unroll
            for (int p = 0; p < 8; p++)
                ldsm4(bF[p], bBL + SWZ128(b_rowoff + p * 2048 + kbase));
            #pragma unroll
            for (int t = 0; t < 16; t++)
                mma_bf16(acc[t], aAh, &bF[t >> 1][(t & 1) * 2]);   // Ahi * Blo
        }
    }

    // fused epilogue: gates + relu + LayerNorm (register/shfl local, __expf)
    int q = lane & 3, rl = lane >> 2;
    #pragma unroll
    for (int h = 0; h < 2; h++) {
        float s1 = 0.f, s2 = 0.f;
        float vals[16];
        #pragma unroll
        for (int j = 0; j < 8; j++) {
            #pragma unroll
            for (int p = 0; p < 2; p++) {
                int col = j * 8 + q * 2 + p;
                float zc = acc[j][h * 2 + p] + g_bcat[col];
                float tc = acc[8 + j][h * 2 + p] + g_bcat[64 + col];
                float z = 1.0f / (1.0f + __expf(-zc));
                float tt = 1.0f - 2.0f / (__expf(2.0f * tc) + 1.0f);
                float v = fmaxf((1.0f - z) * tt, 0.0f);
                vals[j * 2 + p] = v; s1 += v; s2 += v * v;
            }
        }
        s1 += __shfl_xor_sync(0xffffffffu, s1, 1);
        s1 += __shfl_xor_sync(0xffffffffu, s1, 2);
        s2 += __shfl_xor_sync(0xffffffffu, s2, 1);
        s2 += __shfl_xor_sync(0xffffffffu, s2, 2);
        float mu = s1 * (1.0f / 64.0f);
        float var = s2 * (1.0f / 64.0f) - mu * mu;
        float rstd = rsqrtf(var + LN_EPS);
        int node = row0 + m0 + rl + h * 8;
        if (node < NN) {
            float* o = g_h + ((size_t)s * NN + node) * FF;
            #pragma unroll
            for (int j = 0; j < 8; j++) {
                int col = j * 8 + q * 2;
                float2 w;
                w.x = (vals[j * 2 + 0] - mu) * rstd * ln_g[col] + ln_b[col];
                w.y = (vals[j * 2 + 1] - mu) * rstd * ln_g[col + 1] + ln_b[col + 1];
                *(float2*)(o + col) = w;
            }
        }
    }
}

// ---------------- final thin GEMM [16,768000] x [768000,10] -------------------
__global__ void __launch_bounds__(256) k_final1(const float* __restrict__ lin_w) {
    int chunk = blockIdx.x;
    int j0 = chunk * CHUNK_J;
    int tid = threadIdx.x;
    int bg = tid >> 6;
    int kl = tid & 63;
    float acc[4][10];
    #pragma unroll
    for (int bi = 0; bi < 4; bi++)
        #pragma unroll
        for (int c = 0; c < 10; c++) acc[bi][c] = 0.0f;

    for (int k = j0 + kl; k < j0 + CHUNK_J; k += 64) {
        float w[10];
        #pragma unroll
        for (int c = 0; c < 10; c++) w[c] = lin_w[(size_t)c * JTOT + k];
        #pragma unroll
        for (int bi = 0; bi < 4; bi++) {
            float h = g_h[(size_t)(bg * 4 + bi) * JTOT + k];
            #pragma unroll
            for (int c = 0; c < 10; c++) acc[bi][c] += h * w[c];
        }
    }
    __shared__ float red[256 * 40];
    #pragma unroll
    for (int bi = 0; bi < 4; bi++)
        #pragma unroll
        for (int c = 0; c < 10; c++) red[tid * 40 + bi * 10 + c] = acc[bi][c];
    __syncthreads();
    if (tid < 160) {
        int b = tid / 10, c = tid % 10;
        int bg2 = b >> 2, bi2 = b & 3;
        float sum = 0.0f;
        for (int l = 0; l < 64; l++)
            sum += red[(bg2 * 64 + l) * 40 + bi2 * 10 + c];
        g_partial[(chunk * BBATCH + b) * CC + c] = sum;
    }
}

__global__ void k_final2(const float* __restrict__ lin_b, float* __restrict__ out) {
    int i = threadIdx.x;
    if (i < BBATCH * CC) {
        int b = i / CC, c = i % CC;
        float s = lin_b[c];
        for (int ch = 0; ch < FCHUNKS; ch++)
            s += g_partial[(ch * BBATCH + b) * CC + c];
        out[b * CC + c] = s;
    }
}

// ---------------- launch ------------------------------------------------------
extern "C" void kernel_launch(void* const* d_in, const int* in_sizes, int n_in,
                              void* d_out, int out_size) {
    const float* x   = (const float*)d_in[0];
    const int*   ei  = (const int*)d_in[1];
    const float* Wz  = (const float*)d_in[2];
    const float* bz  = (const float*)d_in[3];
    // d_in[4]=W_r, d_in[5]=b_r provably unused (h0 == 0)
    const float* Wh  = (const float*)d_in[6];
    const float* bh  = (const float*)d_in[7];
    const float* lng = (const float*)d_in[8];
    const float* lnb = (const float*)d_in[9];
    const float* lw  = (const float*)d_in[10];
    const float* lb  = (const float*)d_in[11];
    float* out = (float*)d_out;

    cudaFuncSetAttribute(a_prop, cudaFuncAttributeMaxDynamicSharedMemorySize, PROP_SMEM);
    cudaFuncSetAttribute(k_build, cudaFuncAttributeMaxDynamicSharedMemorySize, EE * 8);
    cudaFuncSetAttribute(k_gemm_mma, cudaFuncAttributeMaxDynamicSharedMemorySize, SM_TOTAL_GEMM);

    k_packW<<<(9 * 8192 + 255) / 256, 256>>>(Wz, bz, Wh, bh);   // launch 1
    k_pre<<<1, 1024>>>(ei);                                      // launch 2
    k_build<<<(NN + 7) / 8, 256, EE * 8>>>(ei);                  // launch 3

    for (int lvl = 1; lvl <= 4; lvl++)                           // launches 4-7
        a_prop<<<dim3(SS, 2, 4), 1024, PROP_SMEM>>>(x, lvl);

    k_gemm_mma<<<dim3(SS * 16), 128, SM_TOTAL_GEMM>>>(x, lng, lnb);
    k_final1<<<FCHUNKS, 256>>>(lw);
    k_final2<<<1, 192>>>(lb, out);
}

// round 15
// speedup vs baseline: 1.0958x; 1.0958x over previous
#include <cuda_runtime.h>
#include <cuda_bf16.h>
#include <math.h>
#include <stdint.h>

#define NN 1000
#define FF 64
#define SS 192          // B*T snapshots
#define EE 16000
#define CC 10
#define BBATCH 16
#define JTOT 768000     // T*N*F
#define LN_EPS 1e-5f
#define FCHUNKS 384
#define CHUNK_J 2000

// ---------------- scratch (static device globals; no allocation) -------------
__device__ float g_basis[8][SS * NN * FF];
__device__ float g_h[SS * NN * FF];
__device__ __nv_bfloat16 g_Bpack[2][9][8192];   // [hi/lo][slot][swizzled 128n x 64k]
__device__ float g_bcat[128];
__device__ int   g_offA[NN + 8], g_offB[NN + 8];   // padded for 16B cp.async reads
__device__ uint16_t g_adjA16[EE + 8];            // prop_out srcs (grouped by dst)
__device__ uint16_t g_adjB16[EE + 8];            // prop_in  srcs (grouped by row)
__device__ float g_invdeg_out[NN];
__device__ float g_inv_deg_in[NN];
__device__ float g_partial[FCHUNKS * BBATCH * CC];

// ---------------- helpers -----------------------------------------------------
__device__ __forceinline__ uint32_t smem_u32(const void* p) {
    uint32_t a;
    asm("{ .reg .u64 t; cvta.to.shared.u64 t, %1; cvt.u32.u64 %0, t; }" : "=r"(a) : "l"(p));
    return a;
}
#define SWZ128(o) ((o) ^ (((o) >> 3) & 0x70))

__device__ __forceinline__ void cpa16(uint32_t dst, const void* src) {
    asm volatile("cp.async.cg.shared.global [%0], [%1], 16;" :: "r"(dst), "l"(src));
}
__device__ __forceinline__ void cpa_commit_wait() {
    asm volatile("cp.async.commit_group;" ::: "memory");
    asm volatile("cp.async.wait_group 0;" ::: "memory");
}

__device__ __forceinline__ void ldsm4(uint32_t* r, uint32_t addr) {
    asm volatile("ldmatrix.sync.aligned.m8n8.x4.shared.b16 {%0,%1,%2,%3}, [%4];"
        : "=r"(r[0]), "=r"(r[1]), "=r"(r[2]), "=r"(r[3]) : "r"(addr));
}

__device__ __forceinline__ void mma_bf16(float* d, const uint32_t* a, const uint32_t* b) {
    asm volatile(
        "mma.sync.aligned.m16n8k16.row.col.f32.bf16.bf16.f32 "
        "{%0,%1,%2,%3}, {%4,%5,%6,%7}, {%8,%9}, {%0,%1,%2,%3};"
        : "+f"(d[0]), "+f"(d[1]), "+f"(d[2]), "+f"(d[3])
        : "r"(a[0]), "r"(a[1]), "r"(a[2]), "r"(a[3]), "r"(b[0]), "r"(b[1]));
}

// ---------------- fused graph preprocessing (zero+count+scan, 1 block) --------
__global__ void k_pre(const int* __restrict__ ei) {
    __shared__ int sdo[NN], sdi[NN];
    __shared__ int sA[1024], sB[1024];
    int i = threadIdx.x;
    if (i < NN) { sdo[i] = 0; sdi[i] = 0; }
    __syncthreads();
    for (int e = i; e < EE; e += 1024) {
        atomicAdd(&sdo[ei[e]], 1);
        atomicAdd(&sdi[ei[EE + e]], 1);
    }
    __syncthreads();
    int da = (i < NN) ? sdi[i] : 0;
    int db = (i < NN) ? sdo[i] : 0;
    sA[i] = da; sB[i] = db;
    __syncthreads();
    for (int off = 1; off < 1024; off <<= 1) {
        int va = (i >= off) ? sA[i - off] : 0;
        int vb = (i >= off) ? sB[i - off] : 0;
        __syncthreads();
        sA[i] += va; sB[i] += vb;
        __syncthreads();
    }
    if (i < NN) {
        g_offA[i] = sA[i] - da;
        g_offB[i] = sB[i] - db;
        g_inv_deg_in[i] = 1.0f / (float)da;
        g_invdeg_out[i] = 1.0f / (float)sdo[i];
    }
    if (i == 0) { g_offA[NN] = sA[1023]; g_offB[NN] = sB[1023]; }
}

// deterministic CSR build: stage all edges in smem, one warp per node, ballot compaction
__global__ void k_build(const int* __restrict__ ei) {
    extern __shared__ int2 se[];                   // 16000 x 8B = 128KB
    int tid = threadIdx.x;
    for (int i = tid; i < EE; i += blockDim.x)
        se[i] = make_int2(ei[i], ei[EE + i]);
    __syncthreads();
    int warp = blockIdx.x * (blockDim.x >> 5) + (tid >> 5);
    int lane = tid & 31;
    if (warp >= NN) return;
    int n = warp;
    int pa = g_offA[n], pb = g_offB[n];
    for (int e0 = 0; e0 < EE; e0 += 32) {
        int2 rc = se[e0 + lane];
        unsigned mA = __ballot_sync(0xffffffffu, rc.y == n);
        unsigned mB = __ballot_sync(0xffffffffu, rc.x == n);
        if (rc.y == n) {
            int pos = pa + __popc(mA & ((1u << lane) - 1));
            g_adjA16[pos] = (uint16_t)rc.x;
        }
        if (rc.x == n) {
            int pos = pb + __popc(mB & ((1u << lane) - 1));
            g_adjB16[pos] = (uint16_t)rc.y;
        }
        pa += __popc(mA); pb += __popc(mB);
    }
}

// pack weights into bf16 hi/lo images (SW128-swizzled, [n][k] rows of 128B)
__global__ void k_packW(const float* __restrict__ Wz, const float* __restrict__ bz,
                        const float* __restrict__ Wh, const float* __restrict__ bh) {
    int i = blockIdx.x * blockDim.x + threadIdx.x;
    if (i < 128) g_bcat[i] = (i < 64) ? bz[i] : bh[i - 64];
    if (i >= 9 * 8192) return;
    int slot = i >> 13;
    int r = i & 8191;
    int n = r >> 6, k = r & 63;
    const float* W = (n < 64) ? Wz : Wh;
    int f = n & 63;
    float v;
    if (slot == 0) {
        v = W[(0 * 5 + 0) * 128 * 64 + k * 64 + f]
          + W[(1 * 5 + 0) * 128 * 64 + k * 64 + f];
    } else {
        int kc = (slot + 1) >> 1;
        int dir = (slot - 1) & 1;
        v = W[(dir * 5 + kc) * 128 * 64 + k * 64 + f];
    }
    __nv_bfloat16 hi = __float2bfloat16(v);
    __nv_bfloat16 lo = __float2bfloat16(v - __bfloat162float(hi));
    uint32_t off = SWZ128((uint32_t)(n * 128 + k * 2));
    g_Bpack[0][slot][off >> 1] = hi;
    g_Bpack[1][slot][off >> 1] = lo;
}

// ---------------- Chebyshev propagation (R13-proven: 32-feat halves) ----------
// dir0 plane pre-scaled by 1/deg_out[node]; half-warp 0 -> edge j, half-warp 1
// -> edge j+1, each lane covers 2 features via LDS.64; shfl merge at the end.
#define ADJ_OFF  128000     // 16000 uint16
#define OFF_OFF  160000     // 1008 ints
#define INV_OFF  164032     // 1000 floats
#define PROP_SMEM 168032

__global__ void __launch_bounds__(1024, 1) a_prop(const float* __restrict__ x, int level) {
    extern __shared__ float sv[];
    float2* sv2 = (float2*)sv;                      // [1000][16]
    uint16_t* sadj = (uint16_t*)((char*)sv + ADJ_OFF);
    int* soff = (int*)((char*)sv + OFF_OFF);
    float* sinv = (float*)((char*)sv + INV_OFF);
    int s = blockIdx.x, dir = blockIdx.y, half = blockIdx.z;
    int dst_slot = 2 * level - 1 + dir;
    const float* src;
    const float* prev = nullptr;
    if (level == 1) {
        src = x + (size_t)s * NN * FF;
    } else {
        int ssrc = 2 * (level - 1) - 1 + dir;
        src = g_basis[ssrc - 1] + (size_t)s * NN * FF;
        if (level == 2) prev = x + (size_t)s * NN * FF;
        else prev = g_basis[(2 * (level - 2) - 1) - 1] + (size_t)s * NN * FF;
    }
    uint32_t sb = smem_u32(sv);
    int tid = threadIdx.x;
    #pragma unroll
    for (int it = 0; it < 8; it++) {
        int i = tid + it * 1024;
        if (i < 8000) {
            int n = i >> 3, q = i & 7;
            cpa16(sb + (uint32_t)(n * 128 + q * 16),
                  src + (size_t)n * FF + half * 32 + q * 4);
        }
    }
    {
        const uint16_t* adj = dir ? g_adjB16 : g_adjA16;
        #pragma unroll
        for (int it = 0; it < 2; it++) {
            int i = tid + it * 1024;
            if (i < 2000)
                cpa16(sb + ADJ_OFF + i * 16, adj + i * 8);
        }
    }
    if (tid < 251) {
        const int* offsrc = dir ? g_offB : g_offA;
        cpa16(sb + OFF_OFF + tid * 16, offsrc + tid * 4);
    }
    if (tid >= 512 && tid < 762) {
        const float* invsrc = dir ? g_inv_deg_in : g_invdeg_out;
        int i = tid - 512;
        cpa16(sb + INV_OFF + i * 16, invsrc + i * 4);
    }
    cpa_commit_wait();
    __syncthreads();

    if (dir == 0) {     // pre-scale values by 1/deg_out[node]
        #pragma unroll
        for (int it = 0; it < 32; it++) {
            int i = tid + it * 1024;
            if (i < 32000) sv[i] *= sinv[i >> 5];
        }
        __syncthreads();
    }

    int lane = tid & 31;
    int w = tid >> 5;                     // 32 warps
    int el = lane >> 4, fp = lane & 15;   // edge-slot 0/1, feature-pair 0..15
    float* out = g_basis[dst_slot - 1] + (size_t)s * NN * FF;

    for (int n = w; n < NN; n += 32) {
        int b = soff[n], e = soff[n + 1];
        float ax0 = 0.f, ay0 = 0.f, ax1 = 0.f, ay1 = 0.f;
        int j = b + el;
        for (; j + 2 < e; j += 4) {
            int s0 = sadj[j];
            int s1 = sadj[j + 2];
            float2 v0 = sv2[s0 * 16 + fp];
            float2 v1 = sv2[s1 * 16 + fp];
            ax0 += v0.x; ay0 += v0.y;
            ax1 += v1.x; ay1 += v1.y;
        }
        if (j < e) {
            int s0 = sadj[j];
            float2 v0 = sv2[s0 * 16 + fp];
            ax0 += v0.x; ay0 += v0.y;
        }
        float ax = ax0 + ax1, ay = ay0 + ay1;
        ax += __shfl_xor_sync(0xffffffffu, ax, 16);
        ay += __shfl_xor_sync(0xffffffffu, ay, 16);
        if (dir == 1) { float iv = sinv[n]; ax *= iv; ay *= iv; }
        if (el == 0) {
            int f = half * 32 + fp * 2;
            float2 r;
            if (level == 1) { r.x = ax; r.y = ay; }
            else {
                float2 pv = *(const float2*)(prev + n * FF + f);
                r.x = 2.0f * ax - pv.x;
                r.y = 2.0f * ay - pv.y;
            }
            *(float2*)(out + n * FF + f) = r;
        }
    }
}

// ---------------- mma.sync bf16 GEMM: 128 thr, single-buffer B, 3 CTAs/SM -----
// A prefetched into registers (LDG, hidden behind mma), converted reg->smem.
// B single-buffered via cp.async (48KB total smem -> 3 CTAs/SM for latency
// overlap across co-resident CTAs). 3-pass bf16 split, fp32 accum.
#define SM_AHI 0            // 8192
#define SM_ALO 8192         // 8192
#define SM_B   16384        // 32768 (hi at +0, lo at +16384)
#define SM_TOTAL_GEMM 49152

__global__ void __launch_bounds__(128, 3) k_gemm_mma(const float* __restrict__ x,
                                                     const float* __restrict__ ln_g,
                                                     const float* __restrict__ ln_b) {
    extern __shared__ char smem[];
    uint32_t sb = smem_u32(smem);
    const int tid = threadIdx.x;
    const int wid = tid >> 5, lane = tid & 31;
    const int s = blockIdx.x >> 4;
    const int row0 = (blockIdx.x & 15) << 6;    // 64-row tile
    const int m0 = wid << 4;                    // warp rows within tile

    float acc[16][4];
    #pragma unroll
    for (int t = 0; t < 16; t++)
        #pragma unroll
        for (int c = 0; c < 4; c++) acc[t][c] = 0.0f;

    const uint32_t a_rowoff = (uint32_t)((m0 + (lane & 15)) * 128 + ((lane >> 4) * 16));
    const uint32_t b_rowoff = (uint32_t)((((lane >> 4) * 8 + (lane & 7)) * 128) + (((lane >> 3) & 1) * 16));

    float4 pf[8];
    auto ldA = [&](int slot) {
        const float* plane = (slot == 0) ? (x + (size_t)s * NN * FF)
                                         : (g_basis[slot - 1] + (size_t)s * NN * FF);
        #pragma unroll
        for (int i = 0; i < 8; i++) {
            int j = tid + i * 128;               // 1024 chunks: 64 rows x 16 quads
            int node = row0 + (j >> 4);
            pf[i] = (node < NN) ? *(const float4*)(plane + (size_t)node * FF + (j & 15) * 4)
                                : make_float4(0.f, 0.f, 0.f, 0.f);
        }
    };
    auto issueB = [&](int slot) {
        const char* bh = (const char*)&g_Bpack[0][slot][0];
        const char* bl = (const char*)&g_Bpack[1][slot][0];
        #pragma unroll
        for (int i = 0; i < 8; i++) {
            int j = tid + i * 128;               // 1024 chunks each image
            cpa16(sb + SM_B + j * 16, bh + j * 16);
            cpa16(sb + SM_B + 16384 + j * 16, bl + j * 16);
        }
        asm volatile("cp.async.commit_group;" ::: "memory");
    };

    ldA(0);
    for (int slot = 0; slot < 9; slot++) {
        __syncthreads();                         // B + AHI/ALO free of prev readers
        issueB(slot);                            // B flight overlaps convert below
        #pragma unroll
        for (int i = 0; i < 8; i++) {
            int j = tid + i * 128;
            int m = j >> 4, kq = j & 15;
            float4 v = pf[i];
            __nv_bfloat16 h0 = __float2bfloat16(v.x);
            __nv_bfloat16 h1 = __float2bfloat16(v.y);
            __nv_bfloat16 h2 = __float2bfloat16(v.z);
            __nv_bfloat16 h3 = __float2bfloat16(v.w);
            __nv_bfloat16 l0 = __float2bfloat16(v.x - __bfloat162float(h0));
            __nv_bfloat16 l1 = __float2bfloat16(v.y - __bfloat162float(h1));
            __nv_bfloat16 l2 = __float2bfloat16(v.z - __bfloat162float(h2));
            __nv_bfloat16 l3 = __float2bfloat16(v.w - __bfloat162float(h3));
            uint32_t off = SWZ128((uint32_t)(m * 128 + kq * 8));
            *(__nv_bfloat162*)(smem + SM_AHI + off)     = __halves2bfloat162(h0, h1);
            *(__nv_bfloat162*)(smem + SM_AHI + off + 4) = __halves2bfloat162(h2, h3);
            *(__nv_bfloat162*)(smem + SM_ALO + off)     = __halves2bfloat162(l0, l1);
            *(__nv_bfloat162*)(smem + SM_ALO + off + 4) = __halves2bfloat162(l2, l3);
        }
        if (slot < 8) ldA(slot + 1);             // LDG prefetch; consumed next iter
        asm volatile("cp.async.wait_group 0;" ::: "memory");
        __syncthreads();

        uint32_t bBH = sb + SM_B;
        uint32_t bBL = bBH + 16384;
        #pragma unroll
        for (int kk = 0; kk < 4; kk++) {
            const uint32_t kbase = kk * 32;
            uint32_t aAh[4], aAl[4];
            ldsm4(aAh, sb + SM_AHI + SWZ128(a_rowoff + kbase));
            ldsm4(aAl, sb + SM_ALO + SWZ128(a_rowoff + kbase));
            #pragma unroll
            for (int p = 0; p < 8; p++) {        // per-n-tile-pair B frags (low regs)
                uint32_t bF[4];
                ldsm4(bF, bBH + SWZ128(b_rowoff + p * 2048 + kbase));
                mma_bf16(acc[2 * p],     aAh, &bF[0]);   // Ahi * Bhi
                mma_bf16(acc[2 * p + 1], aAh, &bF[2]);
                mma_bf16(acc[2 * p],     aAl, &bF[0]);   // Alo * Bhi
                mma_bf16(acc[2 * p + 1], aAl, &bF[2]);
            }
            #pragma unroll
            for (int p = 0; p < 8; p++) {
                uint32_t bF[4];
                ldsm4(bF, bBL + SWZ128(b_rowoff + p * 2048 + kbase));
                mma_bf16(acc[2 * p],     aAh, &bF[0]);   // Ahi * Blo
                mma_bf16(acc[2 * p + 1], aAh, &bF[2]);
            }
        }
    }

    // fused epilogue: gates + relu + LayerNorm (register/shfl local, __expf)
    int q = lane & 3, rl = lane >> 2;
    #pragma unroll
    for (int h = 0; h < 2; h++) {
        float s1 = 0.f, s2 = 0.f;
        float vals[16];
        #pragma unroll
        for (int j = 0; j < 8; j++) {
            #pragma unroll
            for (int p = 0; p < 2; p++) {
                int col = j * 8 + q * 2 + p;
                float zc = acc[j][h * 2 + p] + g_bcat[col];
                float tc = acc[8 + j][h * 2 + p] + g_bcat[64 + col];
                float z = 1.0f / (1.0f + __expf(-zc));
                float tt = 1.0f - 2.0f / (__expf(2.0f * tc) + 1.0f);
                float v = fmaxf((1.0f - z) * tt, 0.0f);
                vals[j * 2 + p] = v; s1 += v; s2 += v * v;
            }
        }
        s1 += __shfl_xor_sync(0xffffffffu, s1, 1);
        s1 += __shfl_xor_sync(0xffffffffu, s1, 2);
        s2 += __shfl_xor_sync(0xffffffffu, s2, 1);
        s2 += __shfl_xor_sync(0xffffffffu, s2, 2);
        float mu = s1 * (1.0f / 64.0f);
        float var = s2 * (1.0f / 64.0f) - mu * mu;
        float rstd = rsqrtf(var + LN_EPS);
        int node = row0 + m0 + rl + h * 8;
        if (node < NN) {
            float* o = g_h + ((size_t)s * NN + node) * FF;
            #pragma unroll
            for (int j = 0; j < 8; j++) {
                int col = j * 8 + q * 2;
                float2 w;
                w.x = (vals[j * 2 + 0] - mu) * rstd * ln_g[col] + ln_b[col];
                w.y = (vals[j * 2 + 1] - mu) * rstd * ln_g[col + 1] + ln_b[col + 1];
                *(float2*)(o + col) = w;
            }
        }
    }
}

// ---------------- final thin GEMM [16,768000] x [768000,10] -------------------
__global__ void __launch_bounds__(256) k_final1(const float* __restrict__ lin_w) {
    int chunk = blockIdx.x;
    int j0 = chunk * CHUNK_J;
    int tid = threadIdx.x;
    int bg = tid >> 6;
    int kl = tid & 63;
    float acc[4][10];
    #pragma unroll
    for (int bi = 0; bi < 4; bi++)
        #pragma unroll
        for (int c = 0; c < 10; c++) acc[bi][c] = 0.0f;

    for (int k = j0 + kl; k < j0 + CHUNK_J; k += 64) {
        float w[10];
        #pragma unroll
        for (int c = 0; c < 10; c++) w[c] = lin_w[(size_t)c * JTOT + k];
        #pragma unroll
        for (int bi = 0; bi < 4; bi++) {
            float h = g_h[(size_t)(bg * 4 + bi) * JTOT + k];
            #pragma unroll
            for (int c = 0; c < 10; c++) acc[bi][c] += h * w[c];
        }
    }
    __shared__ float red[256 * 40];
    #pragma unroll
    for (int bi = 0; bi < 4; bi++)
        #pragma unroll
        for (int c = 0; c < 10; c++) red[tid * 40 + bi * 10 + c] = acc[bi][c];
    __syncthreads();
    if (tid < 160) {
        int b = tid / 10, c = tid % 10;
        int bg2 = b >> 2, bi2 = b & 3;
        float sum = 0.0f;
        for (int l = 0; l < 64; l++)
            sum += red[(bg2 * 64 + l) * 40 + bi2 * 10 + c];
        g_partial[(chunk * BBATCH + b) * CC + c] = sum;
    }
}

__global__ void k_final2(const float* __restrict__ lin_b, float* __restrict__ out) {
    int i = threadIdx.x;
    if (i < BBATCH * CC) {
        int b = i / CC, c = i % CC;
        float s = lin_b[c];
        for (int ch = 0; ch < FCHUNKS; ch++)
            s += g_partial[(ch * BBATCH + b) * CC + c];
        out[b * CC + c] = s;
    }
}

// ---------------- launch ------------------------------------------------------
extern "C" void kernel_launch(void* const* d_in, const int* in_sizes, int n_in,
                              void* d_out, int out_size) {
    const float* x   = (const float*)d_in[0];
    const int*   ei  = (const int*)d_in[1];
    const float* Wz  = (const float*)d_in[2];
    const float* bz  = (const float*)d_in[3];
    // d_in[4]=W_r, d_in[5]=b_r provably unused (h0 == 0)
    const float* Wh  = (const float*)d_in[6];
    const float* bh  = (const float*)d_in[7];
    const float* lng = (const float*)d_in[8];
    const float* lnb = (const float*)d_in[9];
    const float* lw  = (const float*)d_in[10];
    const float* lb  = (const float*)d_in[11];
    float* out = (float*)d_out;

    cudaFuncSetAttribute(a_prop, cudaFuncAttributeMaxDynamicSharedMemorySize, PROP_SMEM);
    cudaFuncSetAttribute(k_build, cudaFuncAttributeMaxDynamicSharedMemorySize, EE * 8);
    cudaFuncSetAttribute(k_gemm_mma, cudaFuncAttributeMaxDynamicSharedMemorySize, SM_TOTAL_GEMM);

    k_packW<<<(9 * 8192 + 255) / 256, 256>>>(Wz, bz, Wh, bh);   // launch 1
    k_pre<<<1, 1024>>>(ei);                                      // launch 2
    k_build<<<(NN + 7) / 8, 256, EE * 8>>>(ei);                  // launch 3

    for (int lvl = 1; lvl <= 4; lvl++)                           // launches 4-7
        a_prop<<<dim3(SS, 2, 2), 1024, PROP_SMEM>>>(x, lvl);

    k_gemm_mma<<<dim3(SS * 16), 128, SM_TOTAL_GEMM>>>(x, lng, lnb);
    k_final1<<<FCHUNKS, 256>>>(lw);
    k_final2<<<1, 192>>>(lb, out);
}

// round 16
// speedup vs baseline: 1.1642x; 1.0624x over previous
#include <cuda_runtime.h>
#include <cuda_fp16.h>
#include <cuda_bf16.h>
#include <math.h>
#include <stdint.h>

#define NN 1000
#define FF 64
#define SS 192          // B*T snapshots
#define EE 16000
#define CC 10
#define BBATCH 16
#define JTOT 768000     // T*N*F
#define LN_EPS 1e-5f
#define FCHUNKS 384
#define CHUNK_J 2000

// ---------------- scratch (static device globals; no allocation) -------------
__device__ float g_basis[8][SS * NN * FF];
__device__ float g_h[SS * NN * FF];
__device__ __half g_Bpack[9][8192];              // [slot][swizzled 128n x 64k] fp16
__device__ float g_bcat[128];
__device__ int   g_offA[NN + 8], g_offB[NN + 8];   // padded for 16B cp.async reads
__device__ uint16_t g_adjA16[EE + 8];            // prop_out srcs (grouped by dst)
__device__ uint16_t g_adjB16[EE + 8];            // prop_in  srcs (grouped by row)
__device__ float g_invdeg_out[NN];
__device__ float g_inv_deg_in[NN];
__device__ float g_partial[FCHUNKS * BBATCH * CC];

// ---------------- helpers -----------------------------------------------------
__device__ __forceinline__ uint32_t smem_u32(const void* p) {
    uint32_t a;
    asm("{ .reg .u64 t; cvta.to.shared.u64 t, %1; cvt.u32.u64 %0, t; }" : "=r"(a) : "l"(p));
    return a;
}
#define SWZ128(o) ((o) ^ (((o) >> 3) & 0x70))

__device__ __forceinline__ void cpa16(uint32_t dst, const void* src) {
    asm volatile("cp.async.cg.shared.global [%0], [%1], 16;" :: "r"(dst), "l"(src));
}
__device__ __forceinline__ void cpa_commit_wait() {
    asm volatile("cp.async.commit_group;" ::: "memory");
    asm volatile("cp.async.wait_group 0;" ::: "memory");
}

__device__ __forceinline__ void ldsm4(uint32_t* r, uint32_t addr) {
    asm volatile("ldmatrix.sync.aligned.m8n8.x4.shared.b16 {%0,%1,%2,%3}, [%4];"
        : "=r"(r[0]), "=r"(r[1]), "=r"(r[2]), "=r"(r[3]) : "r"(addr));
}

__device__ __forceinline__ void mma_fp16(float* d, const uint32_t* a, const uint32_t* b) {
    asm volatile(
        "mma.sync.aligned.m16n8k16.row.col.f32.f16.f16.f32 "
        "{%0,%1,%2,%3}, {%4,%5,%6,%7}, {%8,%9}, {%0,%1,%2,%3};"
        : "+f"(d[0]), "+f"(d[1]), "+f"(d[2]), "+f"(d[3])
        : "r"(a[0]), "r"(a[1]), "r"(a[2]), "r"(a[3]), "r"(b[0]), "r"(b[1]));
}

// ---------------- fused graph preprocessing (zero+count+scan, 1 block) --------
__global__ void k_pre(const int* __restrict__ ei) {
    __shared__ int sdo[NN], sdi[NN];
    __shared__ int sA[1024], sB[1024];
    int i = threadIdx.x;
    if (i < NN) { sdo[i] = 0; sdi[i] = 0; }
    __syncthreads();
    for (int e = i; e < EE; e += 1024) {
        atomicAdd(&sdo[ei[e]], 1);
        atomicAdd(&sdi[ei[EE + e]], 1);
    }
    __syncthreads();
    int da = (i < NN) ? sdi[i] : 0;
    int db = (i < NN) ? sdo[i] : 0;
    sA[i] = da; sB[i] = db;
    __syncthreads();
    for (int off = 1; off < 1024; off <<= 1) {
        int va = (i >= off) ? sA[i - off] : 0;
        int vb = (i >= off) ? sB[i - off] : 0;
        __syncthreads();
        sA[i] += va; sB[i] += vb;
        __syncthreads();
    }
    if (i < NN) {
        g_offA[i] = sA[i] - da;
        g_offB[i] = sB[i] - db;
        g_inv_deg_in[i] = 1.0f / (float)da;
        g_invdeg_out[i] = 1.0f / (float)sdo[i];
    }
    if (i == 0) { g_offA[NN] = sA[1023]; g_offB[NN] = sB[1023]; }
}

// deterministic CSR build: stage all edges in smem, one warp per node, ballot compaction
__global__ void k_build(const int* __restrict__ ei) {
    extern __shared__ int2 se[];                   // 16000 x 8B = 128KB
    int tid = threadIdx.x;
    for (int i = tid; i < EE; i += blockDim.x)
        se[i] = make_int2(ei[i], ei[EE + i]);
    __syncthreads();
    int warp = blockIdx.x * (blockDim.x >> 5) + (tid >> 5);
    int lane = tid & 31;
    if (warp >= NN) return;
    int n = warp;
    int pa = g_offA[n], pb = g_offB[n];
    for (int e0 = 0; e0 < EE; e0 += 32) {
        int2 rc = se[e0 + lane];
        unsigned mA = __ballot_sync(0xffffffffu, rc.y == n);
        unsigned mB = __ballot_sync(0xffffffffu, rc.x == n);
        if (rc.y == n) {
            int pos = pa + __popc(mA & ((1u << lane) - 1));
            g_adjA16[pos] = (uint16_t)rc.x;
        }
        if (rc.x == n) {
            int pos = pb + __popc(mB & ((1u << lane) - 1));
            g_adjB16[pos] = (uint16_t)rc.y;
        }
        pa += __popc(mA); pb += __popc(mB);
    }
}

// pack weights into fp16 image (SW128-swizzled, [n][k] rows of 128B)
__global__ void k_packW(const float* __restrict__ Wz, const float* __restrict__ bz,
                        const float* __restrict__ Wh, const float* __restrict__ bh) {
    int i = blockIdx.x * blockDim.x + threadIdx.x;
    if (i < 128) g_bcat[i] = (i < 64) ? bz[i] : bh[i - 64];
    if (i >= 9 * 8192) return;
    int slot = i >> 13;
    int r = i & 8191;
    int n = r >> 6, k = r & 63;
    const float* W = (n < 64) ? Wz : Wh;
    int f = n & 63;
    float v;
    if (slot == 0) {
        v = W[(0 * 5 + 0) * 128 * 64 + k * 64 + f]
          + W[(1 * 5 + 0) * 128 * 64 + k * 64 + f];
    } else {
        int kc = (slot + 1) >> 1;
        int dir = (slot - 1) & 1;
        v = W[(dir * 5 + kc) * 128 * 64 + k * 64 + f];
    }
    uint32_t off = SWZ128((uint32_t)(n * 128 + k * 2));
    g_Bpack[slot][off >> 1] = __float2half(v);
}

// ---------------- Chebyshev propagation (R13-proven: 32-feat halves) ----------
#define ADJ_OFF  128000     // 16000 uint16
#define OFF_OFF  160000     // 1008 ints
#define INV_OFF  164032     // 1000 floats
#define PROP_SMEM 168032

__global__ void __launch_bounds__(1024, 1) a_prop(const float* __restrict__ x, int level) {
    extern __shared__ float sv[];
    float2* sv2 = (float2*)sv;                      // [1000][16]
    uint16_t* sadj = (uint16_t*)((char*)sv + ADJ_OFF);
    int* soff = (int*)((char*)sv + OFF_OFF);
    float* sinv = (float*)((char*)sv + INV_OFF);
    int s = blockIdx.x, dir = blockIdx.y, half = blockIdx.z;
    int dst_slot = 2 * level - 1 + dir;
    const float* src;
    const float* prev = nullptr;
    if (level == 1) {
        src = x + (size_t)s * NN * FF;
    } else {
        int ssrc = 2 * (level - 1) - 1 + dir;
        src = g_basis[ssrc - 1] + (size_t)s * NN * FF;
        if (level == 2) prev = x + (size_t)s * NN * FF;
        else prev = g_basis[(2 * (level - 2) - 1) - 1] + (size_t)s * NN * FF;
    }
    uint32_t sb = smem_u32(sv);
    int tid = threadIdx.x;
    #pragma unroll
    for (int it = 0; it < 8; it++) {
        int i = tid + it * 1024;
        if (i < 8000) {
            int n = i >> 3, q = i & 7;
            cpa16(sb + (uint32_t)(n * 128 + q * 16),
                  src + (size_t)n * FF + half * 32 + q * 4);
        }
    }
    {
        const uint16_t* adj = dir ? g_adjB16 : g_adjA16;
        #pragma unroll
        for (int it = 0; it < 2; it++) {
            int i = tid + it * 1024;
            if (i < 2000)
                cpa16(sb + ADJ_OFF + i * 16, adj + i * 8);
        }
    }
    if (tid < 251) {
        const int* offsrc = dir ? g_offB : g_offA;
        cpa16(sb + OFF_OFF + tid * 16, offsrc + tid * 4);
    }
    if (tid >= 512 && tid < 762) {
        const float* invsrc = dir ? g_inv_deg_in : g_invdeg_out;
        int i = tid - 512;
        cpa16(sb + INV_OFF + i * 16, invsrc + i * 4);
    }
    cpa_commit_wait();
    __syncthreads();

    if (dir == 0) {     // pre-scale values by 1/deg_out[node]
        #pragma unroll
        for (int it = 0; it < 32; it++) {
            int i = tid + it * 1024;
            if (i < 32000) sv[i] *= sinv[i >> 5];
        }
        __syncthreads();
    }

    int lane = tid & 31;
    int w = tid >> 5;                     // 32 warps
    int el = lane >> 4, fp = lane & 15;   // edge-slot 0/1, feature-pair 0..15
    float* out = g_basis[dst_slot - 1] + (size_t)s * NN * FF;

    for (int n = w; n < NN; n += 32) {
        int b = soff[n], e = soff[n + 1];
        float ax0 = 0.f, ay0 = 0.f, ax1 = 0.f, ay1 = 0.f;
        int j = b + el;
        for (; j + 2 < e; j += 4) {
            int s0 = sadj[j];
            int s1 = sadj[j + 2];
            float2 v0 = sv2[s0 * 16 + fp];
            float2 v1 = sv2[s1 * 16 + fp];
            ax0 += v0.x; ay0 += v0.y;
            ax1 += v1.x; ay1 += v1.y;
        }
        if (j < e) {
            int s0 = sadj[j];
            float2 v0 = sv2[s0 * 16 + fp];
            ax0 += v0.x; ay0 += v0.y;
        }
        float ax = ax0 + ax1, ay = ay0 + ay1;
        ax += __shfl_xor_sync(0xffffffffu, ax, 16);
        ay += __shfl_xor_sync(0xffffffffu, ay, 16);
        if (dir == 1) { float iv = sinv[n]; ax *= iv; ay *= iv; }
        if (el == 0) {
            int f = half * 32 + fp * 2;
            float2 r;
            if (level == 1) { r.x = ax; r.y = ay; }
            else {
                float2 pv = *(const float2*)(prev + n * FF + f);
                r.x = 2.0f * ax - pv.x;
                r.y = 2.0f * ay - pv.y;
            }
            *(float2*)(out + n * FF + f) = r;
        }
    }
}

// ---------------- mma.sync fp16 2-pass GEMM: 128 thr, 3 CTAs/SM ---------------
// D = Ahi*B + Alo*B with fp16 split of A (11-bit mantissa x2 ~ fp32), fp16 B.
// Dropped A*Blo term ~2^-12 relative (passes 1e-3 with ~10x margin).
// A prefetched into registers (LDG hidden behind mma), converted reg->smem.
// B double-buffered via cp.async. 48KB smem -> 3 CTAs/SM.
#define SM_AHI 0            // 8192
#define SM_ALO 8192         // 8192
#define SM_B   16384        // 2 x 16384
#define SM_TOTAL_GEMM 49152

__global__ void __launch_bounds__(128, 3) k_gemm_mma(const float* __restrict__ x,
                                                     const float* __restrict__ ln_g,
                                                     const float* __restrict__ ln_b) {
    extern __shared__ char smem[];
    uint32_t sb = smem_u32(smem);
    const int tid = threadIdx.x;
    const int wid = tid >> 5, lane = tid & 31;
    const int s = blockIdx.x >> 4;
    const int row0 = (blockIdx.x & 15) << 6;    // 64-row tile
    const int m0 = wid << 4;                    // warp rows within tile

    float acc[16][4];
    #pragma unroll
    for (int t = 0; t < 16; t++)
        #pragma unroll
        for (int c = 0; c < 4; c++) acc[t][c] = 0.0f;

    const uint32_t a_rowoff = (uint32_t)((m0 + (lane & 15)) * 128 + ((lane >> 4) * 16));
    const uint32_t b_rowoff = (uint32_t)((((lane >> 4) * 8 + (lane & 7)) * 128) + (((lane >> 3) & 1) * 16));

    float4 pf[8];
    auto ldA = [&](int slot) {
        const float* plane = (slot == 0) ? (x + (size_t)s * NN * FF)
                                         : (g_basis[slot - 1] + (size_t)s * NN * FF);
        #pragma unroll
        for (int i = 0; i < 8; i++) {
            int j = tid + i * 128;               // 1024 chunks: 64 rows x 16 quads
            int node = row0 + (j >> 4);
            pf[i] = (node < NN) ? *(const float4*)(plane + (size_t)node * FF + (j & 15) * 4)
                                : make_float4(0.f, 0.f, 0.f, 0.f);
        }
    };
    auto issueB = [&](int slot, int buf) {
        const char* bp = (const char*)&g_Bpack[slot][0];
        #pragma unroll
        for (int i = 0; i < 8; i++) {
            int j = tid + i * 128;               // 1024 chunks
            cpa16(sb + SM_B + buf * 16384 + j * 16, bp + j * 16);
        }
        asm volatile("cp.async.commit_group;" ::: "memory");
    };

    ldA(0);
    issueB(0, 0);
    for (int slot = 0; slot < 9; slot++) {
        int buf = slot & 1;
        __syncthreads();                         // AHI/ALO free of prev-slot readers
        #pragma unroll
        for (int i = 0; i < 8; i++) {
            int j = tid + i * 128;
            int m = j >> 4, kq = j & 15;
            float4 v = pf[i];
            __half h0 = __float2half(v.x);
            __half h1 = __float2half(v.y);
            __half h2 = __float2half(v.z);
            __half h3 = __float2half(v.w);
            __half l0 = __float2half(v.x - __half2float(h0));
            __half l1 = __float2half(v.y - __half2float(h1));
            __half l2 = __float2half(v.z - __half2float(h2));
            __half l3 = __float2half(v.w - __half2float(h3));
            uint32_t off = SWZ128((uint32_t)(m * 128 + kq * 8));
            *(__half2*)(smem + SM_AHI + off)     = __halves2half2(h0, h1);
            *(__half2*)(smem + SM_AHI + off + 4) = __halves2half2(h2, h3);
            *(__half2*)(smem + SM_ALO + off)     = __halves2half2(l0, l1);
            *(__half2*)(smem + SM_ALO + off + 4) = __halves2half2(l2, l3);
        }
        if (slot < 8) {
            ldA(slot + 1);                       // LDG prefetch; consumed next iter
            issueB(slot + 1, buf ^ 1);
            asm volatile("cp.async.wait_group 1;" ::: "memory");
        } else {
            asm volatile("cp.async.wait_group 0;" ::: "memory");
        }
        __syncthreads();

        uint32_t bB = sb + SM_B + buf * 16384;
        #pragma unroll
        for (int kk = 0; kk < 4; kk++) {
            const uint32_t kbase = kk * 32;
            uint32_t aAh[4], aAl[4];
            ldsm4(aAh, sb + SM_AHI + SWZ128(a_rowoff + kbase));
            ldsm4(aAl, sb + SM_ALO + SWZ128(a_rowoff + kbase));
            #pragma unroll
            for (int p = 0; p < 8; p++) {
                uint32_t bF[4];
                ldsm4(bF, bB + SWZ128(b_rowoff + p * 2048 + kbase));
                mma_fp16(acc[2 * p],     aAh, &bF[0]);   // Ahi * B
                mma_fp16(acc[2 * p + 1], aAh, &bF[2]);
                mma_fp16(acc[2 * p],     aAl, &bF[0]);   // Alo * B
                mma_fp16(acc[2 * p + 1], aAl, &bF[2]);
            }
        }
    }

    // fused epilogue: gates + relu + LayerNorm (register/shfl local, __expf)
    int q = lane & 3, rl = lane >> 2;
    #pragma unroll
    for (int h = 0; h < 2; h++) {
        float s1 = 0.f, s2 = 0.f;
        float vals[16];
        #pragma unroll
        for (int j = 0; j < 8; j++) {
            #pragma unroll
            for (int p = 0; p < 2; p++) {
                int col = j * 8 + q * 2 + p;
                float zc = acc[j][h * 2 + p] + g_bcat[col];
                float tc = acc[8 + j][h * 2 + p] + g_bcat[64 + col];
                float z = 1.0f / (1.0f + __expf(-zc));
                float tt = 1.0f - 2.0f / (__expf(2.0f * tc) + 1.0f);
                float v = fmaxf((1.0f - z) * tt, 0.0f);
                vals[j * 2 + p] = v; s1 += v; s2 += v * v;
            }
        }
        s1 += __shfl_xor_sync(0xffffffffu, s1, 1);
        s1 += __shfl_xor_sync(0xffffffffu, s1, 2);
        s2 += __shfl_xor_sync(0xffffffffu, s2, 1);
        s2 += __shfl_xor_sync(0xffffffffu, s2, 2);
        float mu = s1 * (1.0f / 64.0f);
        float var = s2 * (1.0f / 64.0f) - mu * mu;
        float rstd = rsqrtf(var + LN_EPS);
        int node = row0 + m0 + rl + h * 8;
        if (node < NN) {
            float* o = g_h + ((size_t)s * NN + node) * FF;
            #pragma unroll
            for (int j = 0; j < 8; j++) {
                int col = j * 8 + q * 2;
                float2 w;
                w.x = (vals[j * 2 + 0] - mu) * rstd * ln_g[col] + ln_b[col];
                w.y = (vals[j * 2 + 1] - mu) * rstd * ln_g[col + 1] + ln_b[col + 1];
                *(float2*)(o + col) = w;
            }
        }
    }
}

// ---------------- final thin GEMM [16,768000] x [768000,10] -------------------
__global__ void __launch_bounds__(256) k_final1(const float* __restrict__ lin_w) {
    int chunk = blockIdx.x;
    int j0 = chunk * CHUNK_J;
    int tid = threadIdx.x;
    int bg = tid >> 6;
    int kl = tid & 63;
    float acc[4][10];
    #pragma unroll
    for (int bi = 0; bi < 4; bi++)
        #pragma unroll
        for (int c = 0; c < 10; c++) acc[bi][c] = 0.0f;

    for (int k = j0 + kl; k < j0 + CHUNK_J; k += 64) {
        float w[10];
        #pragma unroll
        for (int c = 0; c < 10; c++) w[c] = lin_w[(size_t)c * JTOT + k];
        #pragma unroll
        for (int bi = 0; bi < 4; bi++) {
            float h = g_h[(size_t)(bg * 4 + bi) * JTOT + k];
            #pragma unroll
            for (int c = 0; c < 10; c++) acc[bi][c] += h * w[c];
        }
    }
    __shared__ float red[256 * 40];
    #pragma unroll
    for (int bi = 0; bi < 4; bi++)
        #pragma unroll
        for (int c = 0; c < 10; c++) red[tid * 40 + bi * 10 + c] = acc[bi][c];
    __syncthreads();
    if (tid < 160) {
        int b = tid / 10, c = tid % 10;
        int bg2 = b >> 2, bi2 = b & 3;
        float sum = 0.0f;
        for (int l = 0; l < 64; l++)
            sum += red[(bg2 * 64 + l) * 40 + bi2 * 10 + c];
        g_partial[(chunk * BBATCH + b) * CC + c] = sum;
    }
}

__global__ void k_final2(const float* __restrict__ lin_b, float* __restrict__ out) {
    int i = threadIdx.x;
    if (i < BBATCH * CC) {
        int b = i / CC, c = i % CC;
        float s = lin_b[c];
        for (int ch = 0; ch < FCHUNKS; ch++)
            s += g_partial[(ch * BBATCH + b) * CC + c];
        out[b * CC + c] = s;
    }
}

// ---------------- launch ------------------------------------------------------
extern "C" void kernel_launch(void* const* d_in, const int* in_sizes, int n_in,
                              void* d_out, int out_size) {
    const float* x   = (const float*)d_in[0];
    const int*   ei  = (const int*)d_in[1];
    const float* Wz  = (const float*)d_in[2];
    const float* bz  = (const float*)d_in[3];
    // d_in[4]=W_r, d_in[5]=b_r provably unused (h0 == 0)
    const float* Wh  = (const float*)d_in[6];
    const float* bh  = (const float*)d_in[7];
    const float* lng = (const float*)d_in[8];
    const float* lnb = (const float*)d_in[9];
    const float* lw  = (const float*)d_in[10];
    const float* lb  = (const float*)d_in[11];
    float* out = (float*)d_out;

    cudaFuncSetAttribute(a_prop, cudaFuncAttributeMaxDynamicSharedMemorySize, PROP_SMEM);
    cudaFuncSetAttribute(k_build, cudaFuncAttributeMaxDynamicSharedMemorySize, EE * 8);
    cudaFuncSetAttribute(k_gemm_mma, cudaFuncAttributeMaxDynamicSharedMemorySize, SM_TOTAL_GEMM);

    k_packW<<<(9 * 8192 + 255) / 256, 256>>>(Wz, bz, Wh, bh);   // launch 1
    k_pre<<<1, 1024>>>(ei);                                      // launch 2
    k_build<<<(NN + 7) / 8, 256, EE * 8>>>(ei);                  // launch 3

    for (int lvl = 1; lvl <= 4; lvl++)                           // launches 4-7
        a_prop<<<dim3(SS, 2, 2), 1024, PROP_SMEM>>>(x, lvl);

    k_gemm_mma<<<dim3(SS * 16), 128, SM_TOTAL_GEMM>>>(x, lng, lnb);
    k_final1<<<FCHUNKS, 256>>>(lw);
    k_final2<<<1, 192>>>(lb, out);
}